// round 15
// baseline (speedup 1.0000x reference)
#include <cuda_runtime.h>
#include <cuda_bf16.h>
#include <cstdint>

#define NN 50000
#define EE 800000
#define CC 256

#define PK 40            // padded bf16 B-row stride (80B; conflict-free LDSM)
#define NB_SCAN 49       // ceil(NN/1024)

// resident-A fused kernels (k_mlp3 / k_conv3), 256 threads, 8 warps, 64x64 warp tile
#define PKF 264          // resident A row stride (bf16): 528B
#define AM_B 67584u      // one 128xPKF bf16 matrix
#define AB_TOT 135168u   // A hi+lo
#define MB_STG 40960u    // B stage: Bh(20480)+Bl(20480)
#define MLP_SMEM 217088  // AB_TOT + 2*MB_STG

// ---------------- scratch (device globals; no allocations) ----------------
__device__ __align__(16) float g_s0[(size_t)NN * CC];
__device__ __align__(16) __nv_bfloat16 g_pAh[(size_t)NN * CC];
__device__ __align__(16) __nv_bfloat16 g_pAl[(size_t)NN * CC];
#define WOFF_INNER(l, j) ((size_t)((l)*3 + (j)) * 65536)
#define WOFF_CW1 589824
#define WOFF_CW2 655360
#define WOFF_CW3 671744
#define WTOT 688128
#define WPREP_BLOCKS 2688   // ceil(WTOT/256)
#define COUNT_BLOCKS 3125   // ceil(EE/256)
__device__ __align__(16) __nv_bfloat16 g_wh[WTOT];
__device__ __align__(16) __nv_bfloat16 g_wl[WTOT];
__device__ int g_deg[NN];       // zero; countdown-scatter restores 0 each call
__device__ int g_off[NN + 1];
__device__ int g_csr[EE];
__device__ int g_bsum[64];

// ---------------- PTX helpers ----------------
__device__ __forceinline__ uint32_t s2u(const void* p) {
    uint32_t a;
    asm("{ .reg .u64 t; cvta.to.shared.u64 t, %1; cvt.u32.u64 %0, t; }" : "=r"(a) : "l"(p));
    return a;
}
__device__ __forceinline__ void cp16(uint32_t d, const void* s, uint32_t sz) {
    asm volatile("{ .reg .u64 g; cvta.to.global.u64 g, %1; cp.async.cg.shared.global [%0], [g], 16, %2; }"
                 :: "r"(d), "l"(s), "r"(sz) : "memory");
}
#define CP_COMMIT() asm volatile("cp.async.commit_group;" ::: "memory")
#define CP_WAIT1()  asm volatile("cp.async.wait_group 1;" ::: "memory")
#define CP_WAIT0()  asm volatile("cp.async.wait_group 0;" ::: "memory")

#define MMA(C_, A_, B0_, B1_)                                                    \
    asm volatile(                                                                \
        "mma.sync.aligned.m16n8k16.row.col.f32.bf16.bf16.f32 "                   \
        "{%0,%1,%2,%3}, {%4,%5,%6,%7}, {%8,%9}, {%0,%1,%2,%3};\n"                \
        : "+f"(C_[0]), "+f"(C_[1]), "+f"(C_[2]), "+f"(C_[3])                     \
        : "r"(A_[0]), "r"(A_[1]), "r"(A_[2]), "r"(A_[3]), "r"(B0_), "r"(B1_))

#define LDSM4(R_, a)                                                             \
    asm volatile("ldmatrix.sync.aligned.m8n8.x4.shared.b16 {%0,%1,%2,%3}, [%4];" \
                 : "=r"((R_)[0]), "=r"((R_)[1]), "=r"((R_)[2]), "=r"((R_)[3])    \
                 : "r"(a))

// ---------------- fused count + weight prep (one launch) ----------------
__global__ void k_count_wprep(const int* __restrict__ dst, int* deg,
                              const float* __restrict__ W1s, const float* __restrict__ W2s,
                              const float* __restrict__ W3s, const float* __restrict__ cW1,
                              const float* __restrict__ cW2, const float* __restrict__ cW3,
                              __nv_bfloat16* __restrict__ th, __nv_bfloat16* __restrict__ tl) {
    int b = blockIdx.x;
    if (b < COUNT_BLOCKS) {
        int e = b * 256 + threadIdx.x;
        if (e < EE) atomicAdd(&deg[dst[e]], 1);
        return;
    }
    int i = (b - COUNT_BLOCKS) * 256 + threadIdx.x;
    if (i >= WTOT) return;
    const float* src;
    size_t dsto;
    int K, N, r;
    if (i < 589824) {
        int m = i / 65536;
        r = i - m * 65536;
        int l = m / 3, j = m - l * 3;
        src = (j == 0 ? W1s : j == 1 ? W2s : W3s) + (size_t)l * 65536;
        dsto = (size_t)m * 65536;
        K = 256; N = 256;
    } else if (i < 655360) {
        r = i - 589824; src = cW1; dsto = WOFF_CW1; K = 256; N = 256;
    } else if (i < 671744) {
        r = i - 655360; src = cW2; dsto = WOFF_CW2; K = 256; N = 64;
    } else {
        r = i - 671744; src = cW3; dsto = WOFF_CW3; K = 64; N = 256;
    }
    int k = r / N, n = r - k * N;
    float v = src[r];
    __nv_bfloat16 h = __float2bfloat16(v);
    size_t d = dsto + (size_t)n * K + k;
    th[d] = h;
    tl[d] = __float2bfloat16(v - __bfloat162float(h));
}

// ---------------- CSR build ----------------
__global__ void __launch_bounds__(1024) k_scan1(const int* __restrict__ deg,
                                                int* __restrict__ off,
                                                int* __restrict__ bsum) {
    __shared__ int wtot[32];
    int tid = threadIdx.x, lane = tid & 31, w = tid >> 5;
    int i = blockIdx.x * 1024 + tid;
    int v = (i < NN) ? deg[i] : 0;
    int incl = v;
#pragma unroll
    for (int s = 1; s < 32; s <<= 1) {
        int t = __shfl_up_sync(0xffffffffu, incl, s);
        if (lane >= s) incl += t;
    }
    if (lane == 31) wtot[w] = incl;
    __syncthreads();
    if (tid < 32) {
        int t = wtot[tid];
#pragma unroll
        for (int s = 1; s < 32; s <<= 1) {
            int u = __shfl_up_sync(0xffffffffu, t, s);
            if (tid >= s) t += u;
        }
        wtot[tid] = t;
    }
    __syncthreads();
    int excl = ((w == 0) ? 0 : wtot[w - 1]) + incl - v;
    if (i < NN) off[i] = excl;
    if (tid == 0) bsum[blockIdx.x] = wtot[31];
}
__global__ void __launch_bounds__(64) k_scan2(int* __restrict__ bsum, int* __restrict__ off) {
    __shared__ int s[64];
    int tid = threadIdx.x;
    int v = (tid < NB_SCAN) ? bsum[tid] : 0;
    s[tid] = v;
    __syncthreads();
#pragma unroll
    for (int d = 1; d < 64; d <<= 1) {
        int t = (tid >= d) ? s[tid - d] : 0;
        __syncthreads();
        s[tid] += t;
        __syncthreads();
    }
    if (tid < NB_SCAN) bsum[tid] = s[tid] - v;
    if (tid == NB_SCAN - 1) off[NN] = s[tid];
}
__global__ void k_scatter(const int* __restrict__ src, const int* __restrict__ dst,
                          int* deg, const int* __restrict__ off,
                          const int* __restrict__ bsum, int* __restrict__ csr) {
    int e = blockIdx.x * blockDim.x + threadIdx.x;
    if (e < EE) {
        int d = dst[e];
        int v = atomicSub(&deg[d], 1);
        csr[off[d] + bsum[d >> 10] + v - 1] = src[e];
    }
}

// ---------------- aggregation: fp32 in, split bf16 out ----------------
__device__ __forceinline__ void st_split4(__nv_bfloat16* oh, __nv_bfloat16* ol, float4 a) {
    union { uint2 u; __nv_bfloat16 b[4]; } H, L;
    float f[4] = {a.x, a.y, a.z, a.w};
#pragma unroll
    for (int j = 0; j < 4; j++) {
        __nv_bfloat16 h = __float2bfloat16(f[j]);
        H.b[j] = h;
        L.b[j] = __float2bfloat16(f[j] - __bfloat162float(h));
    }
    *(uint2*)oh = H.u;
    *(uint2*)ol = L.u;
}

__global__ void __launch_bounds__(256) k_agg_split(const float* __restrict__ x,
                                                   const int* __restrict__ off,
                                                   const int* __restrict__ bsum,
                                                   const int* __restrict__ csr,
                                                   __nv_bfloat16* __restrict__ oh,
                                                   __nv_bfloat16* __restrict__ ol) {
    int wid = (blockIdx.x * blockDim.x + threadIdx.x) >> 5;
    int lane = threadIdx.x & 31;
    if (wid >= NN) return;
    const float4* x4 = (const float4*)x;
    size_t rb = (size_t)wid * 64;
    float4 a0 = x4[rb + lane];
    float4 a1 = x4[rb + 32 + lane];
    float4 b0 = make_float4(0.f, 0.f, 0.f, 0.f);
    float4 b1 = make_float4(0.f, 0.f, 0.f, 0.f);
    int s = off[wid] + bsum[wid >> 10];
    int e = (wid + 1 == NN) ? off[NN] : off[wid + 1] + bsum[(wid + 1) >> 10];
    int i = s;
    for (; i + 1 < e; i += 2) {
        size_t u0 = (size_t)csr[i] * 64;
        size_t u1 = (size_t)csr[i + 1] * 64;
        float4 v0 = x4[u0 + lane];
        float4 v1 = x4[u0 + 32 + lane];
        float4 w0 = x4[u1 + lane];
        float4 w1 = x4[u1 + 32 + lane];
        a0.x += v0.x; a0.y += v0.y; a0.z += v0.z; a0.w += v0.w;
        a1.x += v1.x; a1.y += v1.y; a1.z += v1.z; a1.w += v1.w;
        b0.x += w0.x; b0.y += w0.y; b0.z += w0.z; b0.w += w0.w;
        b1.x += w1.x; b1.y += w1.y; b1.z += w1.z; b1.w += w1.w;
    }
    if (i < e) {
        size_t ub = (size_t)csr[i] * 64;
        float4 v0 = x4[ub + lane];
        float4 v1 = x4[ub + 32 + lane];
        a0.x += v0.x; a0.y += v0.y; a0.z += v0.z; a0.w += v0.w;
        a1.x += v1.x; a1.y += v1.y; a1.z += v1.z; a1.w += v1.w;
    }
    a0.x += b0.x; a0.y += b0.y; a0.z += b0.z; a0.w += b0.w;
    a1.x += b1.x; a1.y += b1.y; a1.z += b1.z; a1.w += b1.w;
    size_t ob = (size_t)wid * CC;
    st_split4(oh + ob + lane * 4, ol + ob + lane * 4, a0);
    st_split4(oh + ob + 128 + lane * 4, ol + ob + 128 + lane * 4, a1);
}

// ---------------- resident-A GEMM pieces (256 thr, 8 warps, 2x4, 64x64 tile) ---------
struct FragCtx {
    uint32_t aOffF, bOff, bOff16;
    int lane, warp, wm, wn, g, tig;
};

__device__ __forceinline__ FragCtx mk_ctx(int tid) {
    FragCtx c;
    c.lane = tid & 31; c.warp = tid >> 5;
    c.g = c.lane >> 2; c.tig = c.lane & 3;
    c.wm = c.warp >> 2; c.wn = c.warp & 3;
    c.aOffF = (uint32_t)(((c.wm * 64 + (c.lane & 7) + ((c.lane >> 3) & 1) * 8) * PKF
                         + ((c.lane >> 4) & 1) * 8) * 2);
    c.bOff = (uint32_t)(((c.wn * 64 + (c.lane & 7) + ((c.lane >> 4) & 1) * 8) * PK
                        + ((c.lane >> 3) & 1) * 8) * 2);
    c.bOff16 = (uint32_t)(((c.wn * 16 + (c.lane & 7) + ((c.lane >> 4) & 1) * 8) * PK
                          + ((c.lane >> 3) & 1) * 8) * 2);
    return c;
}

__device__ __forceinline__ void issueB_g(uint32_t sbase, int tid,
                                         const __nv_bfloat16* WhP,
                                         const __nv_bfloat16* WlP,
                                         int Kw, int Nrows, int s, int buf) {
    uint32_t stg = sbase + AB_TOT + (uint32_t)buf * MB_STG;
    int kb = s * 32;
    int half = Nrows * 4;
    for (int ch = tid; ch < half * 2; ch += 256) {
        int sel = (ch >= half) ? 1 : 0;
        int idx = sel ? ch - half : ch;
        int row = idx >> 2, i = idx & 3;
        uint32_t dstp = stg + (uint32_t)sel * 20480u + (uint32_t)row * 80u + (uint32_t)i * 16u;
        const __nv_bfloat16* gp = (sel ? WlP : WhP) + (size_t)row * Kw + kb + i * 8;
        cp16(dstp, gp, 16);
    }
}

__device__ __forceinline__ void loadA_res(uint32_t sbase, int tid, int m0, int M,
                                          const __nv_bfloat16* Ah,
                                          const __nv_bfloat16* Al) {
#pragma unroll
    for (int it = 0; it < 32; it++) {
        int ch = tid + it * 256;
        int sel = ch >> 12;
        int idx = ch & 4095;
        int row = idx >> 5, c16 = idx & 31;
        uint32_t dstp = sbase + (uint32_t)sel * AM_B + (uint32_t)row * 528u + (uint32_t)c16 * 16u;
        int gr = m0 + row;
        const __nv_bfloat16* gp = (sel == 0 ? Ah : Al);
        uint32_t sz = 16;
        if (gr < M) gp += (size_t)gr * 256 + c16 * 8; else sz = 0;
        cp16(dstp, gp, sz);
    }
}

// one BK=32 MMA step, warp tile 64x64, N=256 — batched fragment preload per ks
__device__ __forceinline__ void mma_step256(uint32_t sbase, const FragCtx& fc,
                                            int sA, int buf, float c[4][8][4]) {
    uint32_t aHb = sbase + fc.aOffF;
    uint32_t aLb = sbase + AM_B + fc.aOffF;
    uint32_t bHb = sbase + AB_TOT + (uint32_t)buf * MB_STG + fc.bOff;
    uint32_t bLb = bHb + 20480u;
#pragma unroll
    for (int ks = 0; ks < 2; ks++) {
        uint32_t koA = (uint32_t)((sA * 32 + ks * 16) * 2);
        uint32_t koB = (uint32_t)(ks * 32);
        unsigned aH[4][4], aL[4][4], bH[4][4], bL[4][4];
        // batch all 16 LDSM4 so their latencies overlap each other, not the MMAs
#pragma unroll
        for (int m = 0; m < 4; m++) {
            uint32_t mo = (uint32_t)(m * 16 * PKF * 2) + koA;
            LDSM4(aH[m], aHb + mo);
            LDSM4(aL[m], aLb + mo);
        }
#pragma unroll
        for (int q = 0; q < 4; q++) {
            uint32_t po = (uint32_t)(q * 16 * PK * 2) + koB;
            LDSM4(bH[q], bHb + po);
            LDSM4(bL[q], bLb + po);
        }
        // per-accumulator product order: HH, HL, LH (bit-identical to prior rounds)
#pragma unroll
        for (int q = 0; q < 4; q++) {
#pragma unroll
            for (int m = 0; m < 4; m++) {
                MMA(c[m][2 * q],     aH[m], bH[q][0], bH[q][1]);
                MMA(c[m][2 * q + 1], aH[m], bH[q][2], bH[q][3]);
            }
#pragma unroll
            for (int m = 0; m < 4; m++) {
                MMA(c[m][2 * q],     aH[m], bL[q][0], bL[q][1]);
                MMA(c[m][2 * q + 1], aH[m], bL[q][2], bL[q][3]);
            }
#pragma unroll
            for (int m = 0; m < 4; m++) {
                MMA(c[m][2 * q],     aL[m], bH[q][0], bH[q][1]);
                MMA(c[m][2 * q + 1], aL[m], bH[q][2], bH[q][3]);
            }
        }
    }
}

__device__ __forceinline__ void epi_res(char* smem, const FragCtx& fc,
                                        const float* bp, float c[4][8][4],
                                        int nTiles, int colBase) {
#pragma unroll
    for (int m = 0; m < 4; m++) {
        int rl = fc.wm * 64 + m * 16 + fc.g;
        for (int n = 0; n < nTiles; n++) {
            int col = colBase + n * 8 + 2 * fc.tig;
            float bb0 = bp[col], bb1 = bp[col + 1];
            float v0 = fmaxf(c[m][n][0] + bb0, 0.f), v1 = fmaxf(c[m][n][1] + bb1, 0.f);
            float v2 = fmaxf(c[m][n][2] + bb0, 0.f), v3 = fmaxf(c[m][n][3] + bb1, 0.f);
            __nv_bfloat16 h0 = __float2bfloat16(v0), h1 = __float2bfloat16(v1);
            __nv_bfloat16 h2 = __float2bfloat16(v2), h3 = __float2bfloat16(v3);
            __nv_bfloat16 l0 = __float2bfloat16(v0 - __bfloat162float(h0));
            __nv_bfloat16 l1 = __float2bfloat16(v1 - __bfloat162float(h1));
            __nv_bfloat16 l2 = __float2bfloat16(v2 - __bfloat162float(h2));
            __nv_bfloat16 l3 = __float2bfloat16(v3 - __bfloat162float(h3));
            char* ph = smem + (size_t)rl * 528 + (size_t)col * 2;
            char* pl = ph + AM_B;
            *(__nv_bfloat162*)ph = __halves2bfloat162(h0, h1);
            *(__nv_bfloat162*)pl = __halves2bfloat162(l0, l1);
            *(__nv_bfloat162*)(ph + 8 * 528) = __halves2bfloat162(h2, h3);
            *(__nv_bfloat162*)(pl + 8 * 528) = __halves2bfloat162(l2, l3);
        }
    }
}

__device__ __forceinline__ void zero_c(float c[4][8][4]) {
#pragma unroll
    for (int m = 0; m < 4; m++)
#pragma unroll
        for (int n = 0; n < 8; n++)
#pragma unroll
            for (int i = 0; i < 4; i++) c[m][n][i] = 0.f;
}

// ---------------- layer-fused MLP (inner layers): 3x 256->256 ----------
__global__ void __launch_bounds__(256, 1) k_mlp3(
    const __nv_bfloat16* __restrict__ Ah, const __nv_bfloat16* __restrict__ Al,
    const __nv_bfloat16* __restrict__ Wh, const __nv_bfloat16* __restrict__ Wl,
    const float* __restrict__ b1, const float* __restrict__ b2,
    const float* __restrict__ b3, float* __restrict__ outF, int M) {
    extern __shared__ char smem[];
    uint32_t sbase = s2u(smem);
    int tid = threadIdx.x;
    FragCtx fc = mk_ctx(tid);
    int m0 = blockIdx.x * 128;

    loadA_res(sbase, tid, m0, M, Ah, Al);
    issueB_g(sbase, tid, Wh, Wl, 256, 256, 0, 0);
    CP_COMMIT();

    float c[4][8][4];
    zero_c(c);

#pragma unroll 1
    for (int p = 0; p < 3; p++) {
        const float* bp = (p == 0) ? b1 : (p == 1) ? b2 : b3;
        const __nv_bfloat16* WhP = Wh + (size_t)p * 65536;
        const __nv_bfloat16* WlP = Wl + (size_t)p * 65536;
#pragma unroll 1
        for (int s = 0; s < 8; s++) {
            if (s < 7)      { issueB_g(sbase, tid, WhP, WlP, 256, 256, s + 1, (s + 1) & 1); CP_COMMIT(); CP_WAIT1(); }
            else if (p < 2) { issueB_g(sbase, tid, WhP + 65536, WlP + 65536, 256, 256, 0, 0); CP_COMMIT(); CP_WAIT1(); }
            else            { CP_WAIT0(); }
            __syncthreads();
            mma_step256(sbase, fc, s, s & 1, c);
            __syncthreads();
        }
        if (p < 2) {
            epi_res(smem, fc, bp, c, 8, fc.wn * 64);
            __syncthreads();
            zero_c(c);
        } else {
#pragma unroll
            for (int m = 0; m < 4; m++) {
                int row = m0 + fc.wm * 64 + m * 16 + fc.g;
#pragma unroll
                for (int n = 0; n < 8; n++) {
                    int col = fc.wn * 64 + n * 8 + 2 * fc.tig;
                    float bb0 = bp[col], bb1 = bp[col + 1];
                    if (row < M)
                        *(float2*)(outF + (size_t)row * 256 + col) =
                            make_float2(c[m][n][0] + bb0, c[m][n][1] + bb1);
                    if (row + 8 < M)
                        *(float2*)(outF + (size_t)(row + 8) * 256 + col) =
                            make_float2(c[m][n][2] + bb0, c[m][n][3] + bb1);
                }
            }
        }
    }
}

// ---------------- fused final conv: 256->256 relu, 256->64 relu, 64->256 linear ------
__global__ void __launch_bounds__(256, 1) k_conv3(
    const __nv_bfloat16* __restrict__ Ah, const __nv_bfloat16* __restrict__ Al,
    const __nv_bfloat16* __restrict__ wh, const __nv_bfloat16* __restrict__ wl,
    const float* __restrict__ cb1, const float* __restrict__ cb2,
    const float* __restrict__ cb3, float* __restrict__ outF, int M) {
    extern __shared__ char smem[];
    uint32_t sbase = s2u(smem);
    int tid = threadIdx.x;
    FragCtx fc = mk_ctx(tid);
    int m0 = blockIdx.x * 128;

    const __nv_bfloat16 *w1h = wh + WOFF_CW1, *w1l = wl + WOFF_CW1;
    const __nv_bfloat16 *w2h = wh + WOFF_CW2, *w2l = wl + WOFF_CW2;
    const __nv_bfloat16 *w3h = wh + WOFF_CW3, *w3l = wl + WOFF_CW3;

    loadA_res(sbase, tid, m0, M, Ah, Al);
    issueB_g(sbase, tid, w1h, w1l, 256, 256, 0, 0);
    CP_COMMIT();

    float c[4][8][4];
    zero_c(c);

    // ---- phase 0: cW1, K=256 (8 stages), N=256, relu -> resident smem ----
#pragma unroll 1
    for (int s = 0; s < 8; s++) {
        if (s < 7) { issueB_g(sbase, tid, w1h, w1l, 256, 256, s + 1, (s + 1) & 1); CP_COMMIT(); CP_WAIT1(); }
        else       { issueB_g(sbase, tid, w2h, w2l, 256, 64, 0, 0);               CP_COMMIT(); CP_WAIT1(); }
        __syncthreads();
        mma_step256(sbase, fc, s, s & 1, c);
        __syncthreads();
    }
    epi_res(smem, fc, cb1, c, 8, fc.wn * 64);
    __syncthreads();
    zero_c(c);

    // ---- phase 1: cW2, K=256 (8 stages), N=64 (warp tile 64x16), relu ----
#pragma unroll 1
    for (int s = 0; s < 8; s++) {
        if (s < 7) { issueB_g(sbase, tid, w2h, w2l, 256, 64, s + 1, (s + 1) & 1); CP_COMMIT(); CP_WAIT1(); }
        else       { issueB_g(sbase, tid, w3h, w3l, 64, 256, 0, 0);              CP_COMMIT(); CP_WAIT1(); }
        __syncthreads();
        {
            uint32_t aHb = sbase + fc.aOffF;
            uint32_t aLb = sbase + AM_B + fc.aOffF;
            uint32_t bHb = sbase + AB_TOT + (uint32_t)(s & 1) * MB_STG + fc.bOff16;
            uint32_t bLb = bHb + 20480u;
#pragma unroll
            for (int ks = 0; ks < 2; ks++) {
                uint32_t koA = (uint32_t)((s * 32 + ks * 16) * 2);
                uint32_t koB = (uint32_t)(ks * 32);
                unsigned aH[4][4], aL[4][4];
#pragma unroll
                for (int m = 0; m < 4; m++) {
                    uint32_t mo = (uint32_t)(m * 16 * PKF * 2) + koA;
                    LDSM4(aH[m], aHb + mo);
                    LDSM4(aL[m], aLb + mo);
                }
                unsigned bH[4], bL[4];
                LDSM4(bH, bHb + koB);
                LDSM4(bL, bLb + koB);
#pragma unroll
                for (int m = 0; m < 4; m++) {
                    MMA(c[m][0], aH[m], bH[0], bH[1]);
                    MMA(c[m][1], aH[m], bH[2], bH[3]);
                }
#pragma unroll
                for (int m = 0; m < 4; m++) {
                    MMA(c[m][0], aH[m], bL[0], bL[1]);
                    MMA(c[m][1], aH[m], bL[2], bL[3]);
                }
#pragma unroll
                for (int m = 0; m < 4; m++) {
                    MMA(c[m][0], aL[m], bH[0], bH[1]);
                    MMA(c[m][1], aL[m], bH[2], bH[3]);
                }
            }
        }
        __syncthreads();
    }
    epi_res(smem, fc, cb2, c, 2, fc.wn * 16);   // resident cols 0..63
    __syncthreads();
    zero_c(c);

    // ---- phase 2: cW3, K=64 (2 stages), N=256, linear -> fp32 out ----
#pragma unroll 1
    for (int s = 0; s < 2; s++) {
        if (s == 0) { issueB_g(sbase, tid, w3h, w3l, 64, 256, 1, 1); CP_COMMIT(); CP_WAIT1(); }
        else        { CP_WAIT0(); }
        __syncthreads();
        mma_step256(sbase, fc, s, s & 1, c);
        __syncthreads();
    }
#pragma unroll
    for (int m = 0; m < 4; m++) {
        int row = m0 + fc.wm * 64 + m * 16 + fc.g;
#pragma unroll
        for (int n = 0; n < 8; n++) {
            int col = fc.wn * 64 + n * 8 + 2 * fc.tig;
            float bb0 = cb3[col], bb1 = cb3[col + 1];
            if (row < M)
                *(float2*)(outF + (size_t)row * 256 + col) =
                    make_float2(c[m][n][0] + bb0, c[m][n][1] + bb1);
            if (row + 8 < M)
                *(float2*)(outF + (size_t)(row + 8) * 256 + col) =
                    make_float2(c[m][n][2] + bb0, c[m][n][3] + bb1);
        }
    }
}

// ---------------- launch ----------------
extern "C" void kernel_launch(void* const* d_in, const int* in_sizes, int n_in,
                              void* d_out, int out_size) {
    const float* x   = (const float*)d_in[0];
    const int*   src = (const int*)d_in[1];
    const int*   dst = (const int*)d_in[2];
    const float* W1s = (const float*)d_in[3];
    const float* b1s = (const float*)d_in[4];
    const float* W2s = (const float*)d_in[5];
    const float* b2s = (const float*)d_in[6];
    const float* W3s = (const float*)d_in[7];
    const float* b3s = (const float*)d_in[8];
    const float* cW1 = (const float*)d_in[9];
    const float* cb1 = (const float*)d_in[10];
    const float* cW2 = (const float*)d_in[11];
    const float* cb2 = (const float*)d_in[12];
    const float* cW3 = (const float*)d_in[13];
    const float* cb3 = (const float*)d_in[14];
    float* out = (float*)d_out;

    float* s0;
    __nv_bfloat16 *pAh, *pAl, *wh, *wl;
    int *deg, *off, *csr, *bsum;
    cudaGetSymbolAddress((void**)&s0, g_s0);
    cudaGetSymbolAddress((void**)&pAh, g_pAh);
    cudaGetSymbolAddress((void**)&pAl, g_pAl);
    cudaGetSymbolAddress((void**)&wh, g_wh);
    cudaGetSymbolAddress((void**)&wl, g_wl);
    cudaGetSymbolAddress((void**)&deg, g_deg);
    cudaGetSymbolAddress((void**)&off, g_off);
    cudaGetSymbolAddress((void**)&csr, g_csr);
    cudaGetSymbolAddress((void**)&bsum, g_bsum);

    cudaFuncSetAttribute(k_mlp3, cudaFuncAttributeMaxDynamicSharedMemorySize, MLP_SMEM);
    cudaFuncSetAttribute(k_conv3, cudaFuncAttributeMaxDynamicSharedMemorySize, MLP_SMEM);

    // fused degree-count + weight prep, then scan + countdown scatter
    k_count_wprep<<<COUNT_BLOCKS + WPREP_BLOCKS, 256>>>(dst, deg, W1s, W2s, W3s,
                                                        cW1, cW2, cW3, wh, wl);
    k_scan1<<<NB_SCAN, 1024>>>(deg, off, bsum);
    k_scan2<<<1, 64>>>(bsum, off);
    k_scatter<<<(EE + 255) / 256, 256>>>(src, dst, deg, off, bsum, csr);

    const int GB = (NN + 127) / 128;  // 391
    const int aggBlocks = (NN + 7) / 8;

    k_agg_split<<<aggBlocks, 256>>>(x, off, bsum, csr, pAh, pAl);
    for (int l = 0; l < 3; l++) {
        k_mlp3<<<GB, 256, MLP_SMEM>>>(pAh, pAl,
                                      wh + WOFF_INNER(l, 0), wl + WOFF_INNER(l, 0),
                                      b1s + (size_t)l * CC, b2s + (size_t)l * CC,
                                      b3s + (size_t)l * CC, s0, NN);
        k_agg_split<<<aggBlocks, 256>>>(s0, off, bsum, csr, pAh, pAl);
    }
    k_conv3<<<GB, 256, MLP_SMEM>>>(pAh, pAl, wh, wl, cb1, cb2, cb3, out, NN);
}

// round 16
// speedup vs baseline: 1.4736x; 1.4736x over previous
#include <cuda_runtime.h>
#include <cuda_bf16.h>
#include <cstdint>

#define NN 50000
#define EE 800000
#define CC 256

#define PK 40            // padded bf16 B-row stride (80B; conflict-free LDSM)
#define NB_SCAN 49       // ceil(NN/1024)

// resident-A fused kernels (k_mlp3 / k_conv3), 256 threads, 8 warps, 64x64 warp tile
#define PKF 264          // resident A row stride (bf16): 528B
#define AM_B 67584u      // one 128xPKF bf16 matrix
#define AB_TOT 135168u   // A hi+lo
#define MB_STG 40960u    // B stage: Bh(20480)+Bl(20480)
#define MLP_SMEM 217088  // AB_TOT + 2*MB_STG

// ---------------- scratch (device globals; no allocations) ----------------
__device__ __align__(16) float g_s0[(size_t)NN * CC];
__device__ __align__(16) __nv_bfloat16 g_pAh[(size_t)NN * CC];
__device__ __align__(16) __nv_bfloat16 g_pAl[(size_t)NN * CC];
#define WOFF_INNER(l, j) ((size_t)((l)*3 + (j)) * 65536)
#define WOFF_CW1 589824
#define WOFF_CW2 655360
#define WOFF_CW3 671744
#define WTOT 688128
#define WPREP_BLOCKS 2688   // ceil(WTOT/256)
#define COUNT_BLOCKS 3125   // ceil(EE/256)
__device__ __align__(16) __nv_bfloat16 g_wh[WTOT];
__device__ __align__(16) __nv_bfloat16 g_wl[WTOT];
__device__ int g_deg[NN];       // zero; countdown-scatter restores 0 each call
__device__ int g_off[NN + 1];
__device__ int g_csr[EE];
__device__ int g_bsum[64];

// ---------------- PTX helpers ----------------
__device__ __forceinline__ uint32_t s2u(const void* p) {
    uint32_t a;
    asm("{ .reg .u64 t; cvta.to.shared.u64 t, %1; cvt.u32.u64 %0, t; }" : "=r"(a) : "l"(p));
    return a;
}
__device__ __forceinline__ void cp16(uint32_t d, const void* s, uint32_t sz) {
    asm volatile("{ .reg .u64 g; cvta.to.global.u64 g, %1; cp.async.cg.shared.global [%0], [g], 16, %2; }"
                 :: "r"(d), "l"(s), "r"(sz) : "memory");
}
#define CP_COMMIT() asm volatile("cp.async.commit_group;" ::: "memory")
#define CP_WAIT1()  asm volatile("cp.async.wait_group 1;" ::: "memory")
#define CP_WAIT0()  asm volatile("cp.async.wait_group 0;" ::: "memory")

#define MMA(C_, A_, B0_, B1_)                                                    \
    asm volatile(                                                                \
        "mma.sync.aligned.m16n8k16.row.col.f32.bf16.bf16.f32 "                   \
        "{%0,%1,%2,%3}, {%4,%5,%6,%7}, {%8,%9}, {%0,%1,%2,%3};\n"                \
        : "+f"(C_[0]), "+f"(C_[1]), "+f"(C_[2]), "+f"(C_[3])                     \
        : "r"(A_[0]), "r"(A_[1]), "r"(A_[2]), "r"(A_[3]), "r"(B0_), "r"(B1_))

#define LDSM4(R_, a)                                                             \
    asm volatile("ldmatrix.sync.aligned.m8n8.x4.shared.b16 {%0,%1,%2,%3}, [%4];" \
                 : "=r"((R_)[0]), "=r"((R_)[1]), "=r"((R_)[2]), "=r"((R_)[3])    \
                 : "r"(a))

// ---------------- fused count + weight prep (one launch) ----------------
__global__ void k_count_wprep(const int* __restrict__ dst, int* deg,
                              const float* __restrict__ W1s, const float* __restrict__ W2s,
                              const float* __restrict__ W3s, const float* __restrict__ cW1,
                              const float* __restrict__ cW2, const float* __restrict__ cW3,
                              __nv_bfloat16* __restrict__ th, __nv_bfloat16* __restrict__ tl) {
    int b = blockIdx.x;
    if (b < COUNT_BLOCKS) {
        int e = b * 256 + threadIdx.x;
        if (e < EE) atomicAdd(&deg[dst[e]], 1);
        return;
    }
    int i = (b - COUNT_BLOCKS) * 256 + threadIdx.x;
    if (i >= WTOT) return;
    const float* src;
    size_t dsto;
    int K, N, r;
    if (i < 589824) {
        int m = i / 65536;
        r = i - m * 65536;
        int l = m / 3, j = m - l * 3;
        src = (j == 0 ? W1s : j == 1 ? W2s : W3s) + (size_t)l * 65536;
        dsto = (size_t)m * 65536;
        K = 256; N = 256;
    } else if (i < 655360) {
        r = i - 589824; src = cW1; dsto = WOFF_CW1; K = 256; N = 256;
    } else if (i < 671744) {
        r = i - 655360; src = cW2; dsto = WOFF_CW2; K = 256; N = 64;
    } else {
        r = i - 671744; src = cW3; dsto = WOFF_CW3; K = 64; N = 256;
    }
    int k = r / N, n = r - k * N;
    float v = src[r];
    __nv_bfloat16 h = __float2bfloat16(v);
    size_t d = dsto + (size_t)n * K + k;
    th[d] = h;
    tl[d] = __float2bfloat16(v - __bfloat162float(h));
}

// ---------------- CSR build ----------------
__global__ void __launch_bounds__(1024) k_scan1(const int* __restrict__ deg,
                                                int* __restrict__ off,
                                                int* __restrict__ bsum) {
    __shared__ int wtot[32];
    int tid = threadIdx.x, lane = tid & 31, w = tid >> 5;
    int i = blockIdx.x * 1024 + tid;
    int v = (i < NN) ? deg[i] : 0;
    int incl = v;
#pragma unroll
    for (int s = 1; s < 32; s <<= 1) {
        int t = __shfl_up_sync(0xffffffffu, incl, s);
        if (lane >= s) incl += t;
    }
    if (lane == 31) wtot[w] = incl;
    __syncthreads();
    if (tid < 32) {
        int t = wtot[tid];
#pragma unroll
        for (int s = 1; s < 32; s <<= 1) {
            int u = __shfl_up_sync(0xffffffffu, t, s);
            if (tid >= s) t += u;
        }
        wtot[tid] = t;
    }
    __syncthreads();
    int excl = ((w == 0) ? 0 : wtot[w - 1]) + incl - v;
    if (i < NN) off[i] = excl;
    if (tid == 0) bsum[blockIdx.x] = wtot[31];
}
__global__ void __launch_bounds__(64) k_scan2(int* __restrict__ bsum, int* __restrict__ off) {
    __shared__ int s[64];
    int tid = threadIdx.x;
    int v = (tid < NB_SCAN) ? bsum[tid] : 0;
    s[tid] = v;
    __syncthreads();
#pragma unroll
    for (int d = 1; d < 64; d <<= 1) {
        int t = (tid >= d) ? s[tid - d] : 0;
        __syncthreads();
        s[tid] += t;
        __syncthreads();
    }
    if (tid < NB_SCAN) bsum[tid] = s[tid] - v;
    if (tid == NB_SCAN - 1) off[NN] = s[tid];
}
__global__ void k_scatter(const int* __restrict__ src, const int* __restrict__ dst,
                          int* deg, const int* __restrict__ off,
                          const int* __restrict__ bsum, int* __restrict__ csr) {
    int e = blockIdx.x * blockDim.x + threadIdx.x;
    if (e < EE) {
        int d = dst[e];
        int v = atomicSub(&deg[d], 1);
        csr[off[d] + bsum[d >> 10] + v - 1] = src[e];
    }
}

// ---------------- aggregation: fp32 in, split bf16 out ----------------
__device__ __forceinline__ void st_split4(__nv_bfloat16* oh, __nv_bfloat16* ol, float4 a) {
    union { uint2 u; __nv_bfloat16 b[4]; } H, L;
    float f[4] = {a.x, a.y, a.z, a.w};
#pragma unroll
    for (int j = 0; j < 4; j++) {
        __nv_bfloat16 h = __float2bfloat16(f[j]);
        H.b[j] = h;
        L.b[j] = __float2bfloat16(f[j] - __bfloat162float(h));
    }
    *(uint2*)oh = H.u;
    *(uint2*)ol = L.u;
}

__global__ void __launch_bounds__(256) k_agg_split(const float* __restrict__ x,
                                                   const int* __restrict__ off,
                                                   const int* __restrict__ bsum,
                                                   const int* __restrict__ csr,
                                                   __nv_bfloat16* __restrict__ oh,
                                                   __nv_bfloat16* __restrict__ ol) {
    int wid = (blockIdx.x * blockDim.x + threadIdx.x) >> 5;
    int lane = threadIdx.x & 31;
    if (wid >= NN) return;
    const float4* x4 = (const float4*)x;
    size_t rb = (size_t)wid * 64;
    float4 a0 = x4[rb + lane];
    float4 a1 = x4[rb + 32 + lane];
    float4 b0 = make_float4(0.f, 0.f, 0.f, 0.f);
    float4 b1 = make_float4(0.f, 0.f, 0.f, 0.f);
    int s = off[wid] + bsum[wid >> 10];
    int e = (wid + 1 == NN) ? off[NN] : off[wid + 1] + bsum[(wid + 1) >> 10];
    int i = s;
    for (; i + 1 < e; i += 2) {
        size_t u0 = (size_t)csr[i] * 64;
        size_t u1 = (size_t)csr[i + 1] * 64;
        float4 v0 = x4[u0 + lane];
        float4 v1 = x4[u0 + 32 + lane];
        float4 w0 = x4[u1 + lane];
        float4 w1 = x4[u1 + 32 + lane];
        a0.x += v0.x; a0.y += v0.y; a0.z += v0.z; a0.w += v0.w;
        a1.x += v1.x; a1.y += v1.y; a1.z += v1.z; a1.w += v1.w;
        b0.x += w0.x; b0.y += w0.y; b0.z += w0.z; b0.w += w0.w;
        b1.x += w1.x; b1.y += w1.y; b1.z += w1.z; b1.w += w1.w;
    }
    if (i < e) {
        size_t ub = (size_t)csr[i] * 64;
        float4 v0 = x4[ub + lane];
        float4 v1 = x4[ub + 32 + lane];
        a0.x += v0.x; a0.y += v0.y; a0.z += v0.z; a0.w += v0.w;
        a1.x += v1.x; a1.y += v1.y; a1.z += v1.z; a1.w += v1.w;
    }
    a0.x += b0.x; a0.y += b0.y; a0.z += b0.z; a0.w += b0.w;
    a1.x += b1.x; a1.y += b1.y; a1.z += b1.z; a1.w += b1.w;
    size_t ob = (size_t)wid * CC;
    st_split4(oh + ob + lane * 4, ol + ob + lane * 4, a0);
    st_split4(oh + ob + 128 + lane * 4, ol + ob + 128 + lane * 4, a1);
}

// ---------------- resident-A GEMM pieces (256 thr, 8 warps, 2x4, 64x64 tile) ---------
struct FragCtx {
    uint32_t aOffF, bOff, bOff16;
    int lane, warp, wm, wn, g, tig;
};

__device__ __forceinline__ FragCtx mk_ctx(int tid) {
    FragCtx c;
    c.lane = tid & 31; c.warp = tid >> 5;
    c.g = c.lane >> 2; c.tig = c.lane & 3;
    c.wm = c.warp >> 2; c.wn = c.warp & 3;
    c.aOffF = (uint32_t)(((c.wm * 64 + (c.lane & 7) + ((c.lane >> 3) & 1) * 8) * PKF
                         + ((c.lane >> 4) & 1) * 8) * 2);
    c.bOff = (uint32_t)(((c.wn * 64 + (c.lane & 7) + ((c.lane >> 4) & 1) * 8) * PK
                        + ((c.lane >> 3) & 1) * 8) * 2);
    c.bOff16 = (uint32_t)(((c.wn * 16 + (c.lane & 7) + ((c.lane >> 4) & 1) * 8) * PK
                          + ((c.lane >> 3) & 1) * 8) * 2);
    return c;
}

__device__ __forceinline__ void issueB_g(uint32_t sbase, int tid,
                                         const __nv_bfloat16* WhP,
                                         const __nv_bfloat16* WlP,
                                         int Kw, int Nrows, int s, int buf) {
    uint32_t stg = sbase + AB_TOT + (uint32_t)buf * MB_STG;
    int kb = s * 32;
    int half = Nrows * 4;
    for (int ch = tid; ch < half * 2; ch += 256) {
        int sel = (ch >= half) ? 1 : 0;
        int idx = sel ? ch - half : ch;
        int row = idx >> 2, i = idx & 3;
        uint32_t dstp = stg + (uint32_t)sel * 20480u + (uint32_t)row * 80u + (uint32_t)i * 16u;
        const __nv_bfloat16* gp = (sel ? WlP : WhP) + (size_t)row * Kw + kb + i * 8;
        cp16(dstp, gp, 16);
    }
}

__device__ __forceinline__ void loadA_res(uint32_t sbase, int tid, int m0, int M,
                                          const __nv_bfloat16* Ah,
                                          const __nv_bfloat16* Al) {
#pragma unroll
    for (int it = 0; it < 32; it++) {
        int ch = tid + it * 256;
        int sel = ch >> 12;
        int idx = ch & 4095;
        int row = idx >> 5, c16 = idx & 31;
        uint32_t dstp = sbase + (uint32_t)sel * AM_B + (uint32_t)row * 528u + (uint32_t)c16 * 16u;
        int gr = m0 + row;
        const __nv_bfloat16* gp = (sel == 0 ? Ah : Al);
        uint32_t sz = 16;
        if (gr < M) gp += (size_t)gr * 256 + c16 * 8; else sz = 0;
        cp16(dstp, gp, sz);
    }
}

// one BK=32 MMA step, warp tile 64x64, N=256 — batched fragment preload per ks
__device__ __forceinline__ void mma_step256(uint32_t sbase, const FragCtx& fc,
                                            int sA, int buf, float c[4][8][4]) {
    uint32_t aHb = sbase + fc.aOffF;
    uint32_t aLb = sbase + AM_B + fc.aOffF;
    uint32_t bHb = sbase + AB_TOT + (uint32_t)buf * MB_STG + fc.bOff;
    uint32_t bLb = bHb + 20480u;
#pragma unroll
    for (int ks = 0; ks < 2; ks++) {
        uint32_t koA = (uint32_t)((sA * 32 + ks * 16) * 2);
        uint32_t koB = (uint32_t)(ks * 32);
        unsigned aH[4][4], aL[4][4], bH[4][4], bL[4][4];
        // batch all 16 LDSM4 so their latencies overlap each other, not the MMAs
#pragma unroll
        for (int m = 0; m < 4; m++) {
            uint32_t mo = (uint32_t)(m * 16 * PKF * 2) + koA;
            LDSM4(aH[m], aHb + mo);
            LDSM4(aL[m], aLb + mo);
        }
#pragma unroll
        for (int q = 0; q < 4; q++) {
            uint32_t po = (uint32_t)(q * 16 * PK * 2) + koB;
            LDSM4(bH[q], bHb + po);
            LDSM4(bL[q], bLb + po);
        }
        // per-accumulator product order: HH, HL, LH (bit-identical to prior rounds)
#pragma unroll
        for (int q = 0; q < 4; q++) {
#pragma unroll
            for (int m = 0; m < 4; m++) {
                MMA(c[m][2 * q],     aH[m], bH[q][0], bH[q][1]);
                MMA(c[m][2 * q + 1], aH[m], bH[q][2], bH[q][3]);
            }
#pragma unroll
            for (int m = 0; m < 4; m++) {
                MMA(c[m][2 * q],     aH[m], bL[q][0], bL[q][1]);
                MMA(c[m][2 * q + 1], aH[m], bL[q][2], bL[q][3]);
            }
#pragma unroll
            for (int m = 0; m < 4; m++) {
                MMA(c[m][2 * q],     aL[m], bH[q][0], bH[q][1]);
                MMA(c[m][2 * q + 1], aL[m], bH[q][2], bH[q][3]);
            }
        }
    }
}

__device__ __forceinline__ void epi_res(char* smem, const FragCtx& fc,
                                        const float* bp, float c[4][8][4],
                                        int nTiles, int colBase) {
#pragma unroll
    for (int m = 0; m < 4; m++) {
        int rl = fc.wm * 64 + m * 16 + fc.g;
        for (int n = 0; n < nTiles; n++) {
            int col = colBase + n * 8 + 2 * fc.tig;
            float bb0 = bp[col], bb1 = bp[col + 1];
            float v0 = fmaxf(c[m][n][0] + bb0, 0.f), v1 = fmaxf(c[m][n][1] + bb1, 0.f);
            float v2 = fmaxf(c[m][n][2] + bb0, 0.f), v3 = fmaxf(c[m][n][3] + bb1, 0.f);
            __nv_bfloat16 h0 = __float2bfloat16(v0), h1 = __float2bfloat16(v1);
            __nv_bfloat16 h2 = __float2bfloat16(v2), h3 = __float2bfloat16(v3);
            __nv_bfloat16 l0 = __float2bfloat16(v0 - __bfloat162float(h0));
            __nv_bfloat16 l1 = __float2bfloat16(v1 - __bfloat162float(h1));
            __nv_bfloat16 l2 = __float2bfloat16(v2 - __bfloat162float(h2));
            __nv_bfloat16 l3 = __float2bfloat16(v3 - __bfloat162float(h3));
            char* ph = smem + (size_t)rl * 528 + (size_t)col * 2;
            char* pl = ph + AM_B;
            *(__nv_bfloat162*)ph = __halves2bfloat162(h0, h1);
            *(__nv_bfloat162*)pl = __halves2bfloat162(l0, l1);
            *(__nv_bfloat162*)(ph + 8 * 528) = __halves2bfloat162(h2, h3);
            *(__nv_bfloat162*)(pl + 8 * 528) = __halves2bfloat162(l2, l3);
        }
    }
}

__device__ __forceinline__ void zero_c(float c[4][8][4]) {
#pragma unroll
    for (int m = 0; m < 4; m++)
#pragma unroll
        for (int n = 0; n < 8; n++)
#pragma unroll
            for (int i = 0; i < 4; i++) c[m][n][i] = 0.f;
}

// ---------------- layer-fused MLP (inner layers): 3x 256->256 ----------
__global__ void __launch_bounds__(256, 1) k_mlp3(
    const __nv_bfloat16* __restrict__ Ah, const __nv_bfloat16* __restrict__ Al,
    const __nv_bfloat16* __restrict__ Wh, const __nv_bfloat16* __restrict__ Wl,
    const float* __restrict__ b1, const float* __restrict__ b2,
    const float* __restrict__ b3, float* __restrict__ outF, int M) {
    extern __shared__ char smem[];
    uint32_t sbase = s2u(smem);
    int tid = threadIdx.x;
    FragCtx fc = mk_ctx(tid);
    int m0 = blockIdx.x * 128;

    loadA_res(sbase, tid, m0, M, Ah, Al);
    issueB_g(sbase, tid, Wh, Wl, 256, 256, 0, 0);
    CP_COMMIT();

    float c[4][8][4];
    zero_c(c);

#pragma unroll 1
    for (int p = 0; p < 3; p++) {
        const float* bp = (p == 0) ? b1 : (p == 1) ? b2 : b3;
        const __nv_bfloat16* WhP = Wh + (size_t)p * 65536;
        const __nv_bfloat16* WlP = Wl + (size_t)p * 65536;
#pragma unroll 1
        for (int s = 0; s < 8; s++) {
            if (s < 7)      { issueB_g(sbase, tid, WhP, WlP, 256, 256, s + 1, (s + 1) & 1); CP_COMMIT(); CP_WAIT1(); }
            else if (p < 2) { issueB_g(sbase, tid, WhP + 65536, WlP + 65536, 256, 256, 0, 0); CP_COMMIT(); CP_WAIT1(); }
            else            { CP_WAIT0(); }
            __syncthreads();
            mma_step256(sbase, fc, s, s & 1, c);
            __syncthreads();
        }
        if (p < 2) {
            epi_res(smem, fc, bp, c, 8, fc.wn * 64);
            __syncthreads();
            zero_c(c);
        } else {
#pragma unroll
            for (int m = 0; m < 4; m++) {
                int row = m0 + fc.wm * 64 + m * 16 + fc.g;
#pragma unroll
                for (int n = 0; n < 8; n++) {
                    int col = fc.wn * 64 + n * 8 + 2 * fc.tig;
                    float bb0 = bp[col], bb1 = bp[col + 1];
                    if (row < M)
                        *(float2*)(outF + (size_t)row * 256 + col) =
                            make_float2(c[m][n][0] + bb0, c[m][n][1] + bb1);
                    if (row + 8 < M)
                        *(float2*)(outF + (size_t)(row + 8) * 256 + col) =
                            make_float2(c[m][n][2] + bb0, c[m][n][3] + bb1);
                }
            }
        }
    }
}

// ---------------- fused final conv: 256->256 relu, 256->64 relu, 64->256 linear ------
__global__ void __launch_bounds__(256, 1) k_conv3(
    const __nv_bfloat16* __restrict__ Ah, const __nv_bfloat16* __restrict__ Al,
    const __nv_bfloat16* __restrict__ wh, const __nv_bfloat16* __restrict__ wl,
    const float* __restrict__ cb1, const float* __restrict__ cb2,
    const float* __restrict__ cb3, float* __restrict__ outF, int M) {
    extern __shared__ char smem[];
    uint32_t sbase = s2u(smem);
    int tid = threadIdx.x;
    FragCtx fc = mk_ctx(tid);
    int m0 = blockIdx.x * 128;

    const __nv_bfloat16 *w1h = wh + WOFF_CW1, *w1l = wl + WOFF_CW1;
    const __nv_bfloat16 *w2h = wh + WOFF_CW2, *w2l = wl + WOFF_CW2;
    const __nv_bfloat16 *w3h = wh + WOFF_CW3, *w3l = wl + WOFF_CW3;

    loadA_res(sbase, tid, m0, M, Ah, Al);
    issueB_g(sbase, tid, w1h, w1l, 256, 256, 0, 0);
    CP_COMMIT();

    float c[4][8][4];
    zero_c(c);

    // ---- phase 0: cW1, K=256 (8 stages), N=256, relu -> resident smem ----
#pragma unroll 1
    for (int s = 0; s < 8; s++) {
        if (s < 7) { issueB_g(sbase, tid, w1h, w1l, 256, 256, s + 1, (s + 1) & 1); CP_COMMIT(); CP_WAIT1(); }
        else       { issueB_g(sbase, tid, w2h, w2l, 256, 64, 0, 0);               CP_COMMIT(); CP_WAIT1(); }
        __syncthreads();
        mma_step256(sbase, fc, s, s & 1, c);
        __syncthreads();
    }
    epi_res(smem, fc, cb1, c, 8, fc.wn * 64);
    __syncthreads();
    zero_c(c);

    // ---- phase 1: cW2, K=256 (8 stages), N=64 (warp tile 64x16), relu ----
#pragma unroll 1
    for (int s = 0; s < 8; s++) {
        if (s < 7) { issueB_g(sbase, tid, w2h, w2l, 256, 64, s + 1, (s + 1) & 1); CP_COMMIT(); CP_WAIT1(); }
        else       { issueB_g(sbase, tid, w3h, w3l, 64, 256, 0, 0);              CP_COMMIT(); CP_WAIT1(); }
        __syncthreads();
        {
            uint32_t aHb = sbase + fc.aOffF;
            uint32_t aLb = sbase + AM_B + fc.aOffF;
            uint32_t bHb = sbase + AB_TOT + (uint32_t)(s & 1) * MB_STG + fc.bOff16;
            uint32_t bLb = bHb + 20480u;
#pragma unroll
            for (int ks = 0; ks < 2; ks++) {
                uint32_t koA = (uint32_t)((s * 32 + ks * 16) * 2);
                uint32_t koB = (uint32_t)(ks * 32);
                unsigned aH[4][4], aL[4][4];
#pragma unroll
                for (int m = 0; m < 4; m++) {
                    uint32_t mo = (uint32_t)(m * 16 * PKF * 2) + koA;
                    LDSM4(aH[m], aHb + mo);
                    LDSM4(aL[m], aLb + mo);
                }
                unsigned bH[4], bL[4];
                LDSM4(bH, bHb + koB);
                LDSM4(bL, bLb + koB);
#pragma unroll
                for (int m = 0; m < 4; m++) {
                    MMA(c[m][0], aH[m], bH[0], bH[1]);
                    MMA(c[m][1], aH[m], bH[2], bH[3]);
                }
#pragma unroll
                for (int m = 0; m < 4; m++) {
                    MMA(c[m][0], aH[m], bL[0], bL[1]);
                    MMA(c[m][1], aH[m], bL[2], bL[3]);
                }
#pragma unroll
                for (int m = 0; m < 4; m++) {
                    MMA(c[m][0], aL[m], bH[0], bH[1]);
                    MMA(c[m][1], aL[m], bH[2], bH[3]);
                }
            }
        }
        __syncthreads();
    }
    epi_res(smem, fc, cb2, c, 2, fc.wn * 16);   // resident cols 0..63
    __syncthreads();
    zero_c(c);

    // ---- phase 2: cW3, K=64 (2 stages), N=256, linear -> fp32 out ----
#pragma unroll 1
    for (int s = 0; s < 2; s++) {
        if (s == 0) { issueB_g(sbase, tid, w3h, w3l, 64, 256, 1, 1); CP_COMMIT(); CP_WAIT1(); }
        else        { CP_WAIT0(); }
        __syncthreads();
        mma_step256(sbase, fc, s, s & 1, c);
        __syncthreads();
    }
#pragma unroll
    for (int m = 0; m < 4; m++) {
        int row = m0 + fc.wm * 64 + m * 16 + fc.g;
#pragma unroll
        for (int n = 0; n < 8; n++) {
            int col = fc.wn * 64 + n * 8 + 2 * fc.tig;
            float bb0 = cb3[col], bb1 = cb3[col + 1];
            if (row < M)
                *(float2*)(outF + (size_t)row * 256 + col) =
                    make_float2(c[m][n][0] + bb0, c[m][n][1] + bb1);
            if (row + 8 < M)
                *(float2*)(outF + (size_t)(row + 8) * 256 + col) =
                    make_float2(c[m][n][2] + bb0, c[m][n][3] + bb1);
        }
    }
}

// ---------------- launch ----------------
extern "C" void kernel_launch(void* const* d_in, const int* in_sizes, int n_in,
                              void* d_out, int out_size) {
    const float* x   = (const float*)d_in[0];
    const int*   src = (const int*)d_in[1];
    const int*   dst = (const int*)d_in[2];
    const float* W1s = (const float*)d_in[3];
    const float* b1s = (const float*)d_in[4];
    const float* W2s = (const float*)d_in[5];
    const float* b2s = (const float*)d_in[6];
    const float* W3s = (const float*)d_in[7];
    const float* b3s = (const float*)d_in[8];
    const float* cW1 = (const float*)d_in[9];
    const float* cb1 = (const float*)d_in[10];
    const float* cW2 = (const float*)d_in[11];
    const float* cb2 = (const float*)d_in[12];
    const float* cW3 = (const float*)d_in[13];
    const float* cb3 = (const float*)d_in[14];
    float* out = (float*)d_out;

    float* s0;
    __nv_bfloat16 *pAh, *pAl, *wh, *wl;
    int *deg, *off, *csr, *bsum;
    cudaGetSymbolAddress((void**)&s0, g_s0);
    cudaGetSymbolAddress((void**)&pAh, g_pAh);
    cudaGetSymbolAddress((void**)&pAl, g_pAl);
    cudaGetSymbolAddress((void**)&wh, g_wh);
    cudaGetSymbolAddress((void**)&wl, g_wl);
    cudaGetSymbolAddress((void**)&deg, g_deg);
    cudaGetSymbolAddress((void**)&off, g_off);
    cudaGetSymbolAddress((void**)&csr, g_csr);
    cudaGetSymbolAddress((void**)&bsum, g_bsum);

    cudaFuncSetAttribute(k_mlp3, cudaFuncAttributeMaxDynamicSharedMemorySize, MLP_SMEM);
    cudaFuncSetAttribute(k_conv3, cudaFuncAttributeMaxDynamicSharedMemorySize, MLP_SMEM);

    // fused degree-count + weight prep, then scan + countdown scatter
    k_count_wprep<<<COUNT_BLOCKS + WPREP_BLOCKS, 256>>>(dst, deg, W1s, W2s, W3s,
                                                        cW1, cW2, cW3, wh, wl);
    k_scan1<<<NB_SCAN, 1024>>>(deg, off, bsum);
    k_scan2<<<1, 64>>>(bsum, off);
    k_scatter<<<(EE + 255) / 256, 256>>>(src, dst, deg, off, bsum, csr);

    const int GB = (NN + 127) / 128;  // 391
    const int aggBlocks = (NN + 7) / 8;

    k_agg_split<<<aggBlocks, 256>>>(x, off, bsum, csr, pAh, pAl);
    for (int l = 0; l < 3; l++) {
        k_mlp3<<<GB, 256, MLP_SMEM>>>(pAh, pAl,
                                      wh + WOFF_INNER(l, 0), wl + WOFF_INNER(l, 0),
                                      b1s + (size_t)l * CC, b2s + (size_t)l * CC,
                                      b3s + (size_t)l * CC, s0, NN);
        k_agg_split<<<aggBlocks, 256>>>(s0, off, bsum, csr, pAh, pAl);
    }
    k_conv3<<<GB, 256, MLP_SMEM>>>(pAh, pAl, wh, wl, cb1, cb2, cb3, out, NN);
}